// round 3
// baseline (speedup 1.0000x reference)
#include <cuda_runtime.h>
#include <cstdint>

#define TOKENS 4096
#define DM 4096
#define DF 16384

// Scratch (device globals: allocation-free rule)
__device__ float g_W1T[(size_t)DF * DM];    // W1^T: [DF][DM], tf32-rounded
__device__ float g_W2T[(size_t)DM * DF];    // W2^T: [DM][DF], tf32-rounded
__device__ float g_h[(size_t)TOKENS * DF];  // intermediate activations (tf32-rounded)
__device__ float g_xr[(size_t)TOKENS * DM]; // x, tf32-rounded

// ---------------- helpers ----------------
__device__ __forceinline__ uint32_t smem_u32(const void* p) {
    uint32_t a;
    asm("{ .reg .u64 t; cvta.to.shared.u64 t, %1; cvt.u32.u64 %0, t; }" : "=r"(a) : "l"(p));
    return a;
}
__device__ __forceinline__ uint32_t sw128(uint32_t off) { return off ^ ((off >> 3) & 0x70); }

__device__ __forceinline__ float rna_tf32(float x) {
    uint32_t u;
    asm("cvt.rna.tf32.f32 %0, %1;" : "=r"(u) : "f"(x));
    return __uint_as_float(u);
}

__device__ __forceinline__ void cp16(uint32_t s, const void* g) {
    asm volatile("cp.async.cg.shared.global [%0], [%1], 16;" :: "r"(s), "l"(g));
}
#define CP_COMMIT() asm volatile("cp.async.commit_group;" ::: "memory")
#define CP_WAIT(n)  asm volatile("cp.async.wait_group %0;" :: "n"(n) : "memory")

#define LDSM4(r, addr) \
    asm volatile("ldmatrix.sync.aligned.m8n8.x4.shared.b16 {%0,%1,%2,%3}, [%4];" \
        : "=r"((r)[0]), "=r"((r)[1]), "=r"((r)[2]), "=r"((r)[3]) : "r"(addr))

__device__ __forceinline__ void mma8(float* c, const uint32_t* a, uint32_t b0, uint32_t b1) {
    asm volatile(
        "mma.sync.aligned.m16n8k8.row.col.f32.tf32.tf32.f32 "
        "{%0,%1,%2,%3}, {%4,%5,%6,%7}, {%8,%9}, {%0,%1,%2,%3};"
        : "+f"(c[0]), "+f"(c[1]), "+f"(c[2]), "+f"(c[3])
        : "r"(a[0]), "r"(a[1]), "r"(a[2]), "r"(a[3]), "r"(b0), "r"(b1));
}

__device__ __forceinline__ float gelu_tanh(float v) {
    float u = 0.7978845608028654f * (v + 0.044715f * v * v * v);
    float e = __expf(-2.0f * fabsf(u));
    float t = (1.0f - e) / (1.0f + e);
    t = copysignf(t, u);
    return 0.5f * v * (1.0f + t);
}

// ---------------- transpose + tf32 round: src[R][C] -> dst[C][R] ----------------
__global__ void transpose_k(const float* __restrict__ src, float* __restrict__ dst,
                            int R, int C) {
    __shared__ float tile[32][33];
    int c0 = blockIdx.x * 32, r0 = blockIdx.y * 32;
    int tx = threadIdx.x & 31, ty = threadIdx.x >> 5;  // 256 threads
#pragma unroll
    for (int i = 0; i < 32; i += 8)
        tile[ty + i][tx] = src[(size_t)(r0 + ty + i) * C + c0 + tx];
    __syncthreads();
#pragma unroll
    for (int i = 0; i < 32; i += 8)
        dst[(size_t)(c0 + ty + i) * R + r0 + tx] = rna_tf32(tile[tx][ty + i]);
}

// ---------------- tf32 round (elementwise, float4) ----------------
__global__ void round_k(const float* __restrict__ src, float* __restrict__ dst, int n4) {
    int i = blockIdx.x * blockDim.x + threadIdx.x;
    if (i < n4) {
        float4 v = ((const float4*)src)[i];
        v.x = rna_tf32(v.x); v.y = rna_tf32(v.y);
        v.z = rna_tf32(v.z); v.w = rna_tf32(v.w);
        ((float4*)dst)[i] = v;
    }
}

// ---------------- tf32 mma.sync GEMM ----------------
// C[M,N] = act(A[M,K] @ Bt[N,K]^T + bias); A, Bt K-major row-major, K%32==0.
constexpr int TM = 128, TN = 128, TK = 32, NSTG = 3;
constexpr int A_BYTES = TM * TK * 4;             // 16384
constexpr int B_BYTES = TN * TK * 4;             // 16384
constexpr int STAGE_BYTES = A_BYTES + B_BYTES;   // 32768
constexpr int SM_BIAS   = 0;                     // 128 floats
constexpr int SM_STAGES = 1024;
constexpr int SMEM_TOTAL = SM_STAGES + NSTG * STAGE_BYTES;  // 99328

template <bool GELU_ROUND>
__global__ void __launch_bounds__(256)
ffn_gemm(const float* __restrict__ A, const float* __restrict__ Bt,
         const float* __restrict__ bias, float* __restrict__ C,
         int M, int N, int K) {
    extern __shared__ char smem[];
    uint32_t sb = smem_u32(smem);
    int tid = threadIdx.x;
    int wid = tid >> 5, lid = tid & 31;
    int warp_m = wid & 1, warp_n = wid >> 1;   // 2 x 4 warp grid, warp tile 64x32

    // L2-friendly tile swizzle: groups of 8 N-tiles x all M-tiles
    int tiles_m = M / TM;
    const int GW = 8;
    int per_group = GW * tiles_m;
    int g = blockIdx.x / per_group;
    int r = blockIdx.x % per_group;
    int nt = g * GW + (r % GW);
    int mt = r / GW;
    int m0 = mt * TM, n0 = nt * TN;

    // bias tile -> smem
    float* bsm = (float*)(smem + SM_BIAS);
    if (tid < TN) bsm[tid] = bias[n0 + tid];

    // per-lane ldmatrix byte offsets, UNSWIZZLED (swizzle applied at use site,
    // because sw128(off + d) != sw128(off) + d when the XOR mask carries).
    // A frag m16n8k8 tf32: r0=(g,t4) r1=(g+8,t4) r2=(g,t4+4) r3=(g+8,t4+4)
    uint32_t aoff[4], boff[2];
    {
        int l = lid;
        int rA = ((l >> 3) & 1) * 8 + (l & 7);
        int cA = ((l >> 4) & 1) * 4;
#pragma unroll
        for (int mf = 0; mf < 4; mf++)
            aoff[mf] = (uint32_t)(warp_m * 64 + mf * 16 + rA) * 128 + cA * 4;
        int rB = ((l >> 4) & 1) * 8 + (l & 7);
        int cB = ((l >> 3) & 1) * 4;
#pragma unroll
        for (int np = 0; np < 2; np++)
            boff[np] = (uint32_t)(warp_n * 32 + np * 16 + rB) * 128 + cB * 4;
    }

    float acc[4][4][4];
#pragma unroll
    for (int i = 0; i < 4; i++)
#pragma unroll
        for (int j = 0; j < 4; j++)
#pragma unroll
            for (int k = 0; k < 4; k++) acc[i][j][k] = 0.0f;

    int nch = K / TK;

    auto load_stage = [&](int stage, int ch) {
        uint32_t abase = sb + SM_STAGES + stage * STAGE_BYTES;
        uint32_t bbase = abase + A_BYTES;
        const float* Ap = A + (size_t)m0 * K + ch * TK;
        const float* Bp = Bt + (size_t)n0 * K + ch * TK;
#pragma unroll
        for (int j = 0; j < 4; j++) {  // A: 1024 x 16B
            int e = tid + j * 256;
            int row = e >> 3, c = e & 7;
            cp16(abase + sw128(row * 128 + c * 16), Ap + (size_t)row * K + c * 4);
        }
#pragma unroll
        for (int j = 0; j < 4; j++) {  // B: 1024 x 16B
            int e = tid + j * 256;
            int row = e >> 3, c = e & 7;
            cp16(bbase + sw128(row * 128 + c * 16), Bp + (size_t)row * K + c * 4);
        }
    };

    // prologue
    for (int s = 0; s < NSTG - 1; s++) { load_stage(s, s); CP_COMMIT(); }

    for (int ch = 0; ch < nch; ch++) {
        CP_WAIT(1);           // stage ch resident (NSTG-2 pending)
        __syncthreads();      // all lanes see it; prior compute on overwrite-target done

        int pf = ch + NSTG - 1;
        if (pf < nch) load_stage(pf % NSTG, pf);
        CP_COMMIT();

        uint32_t ab = sb + SM_STAGES + (ch % NSTG) * STAGE_BYTES;
        uint32_t bb = ab + A_BYTES;
#pragma unroll
        for (int ks = 0; ks < 4; ks++) {
            uint32_t Af[4][4], Bf[2][4];
#pragma unroll
            for (int mf = 0; mf < 4; mf++)
                LDSM4(Af[mf], ab + sw128(aoff[mf] + ks * 32));
#pragma unroll
            for (int np = 0; np < 2; np++)
                LDSM4(Bf[np], bb + sw128(boff[np] + ks * 32));
#pragma unroll
            for (int mf = 0; mf < 4; mf++)
#pragma unroll
                for (int nf = 0; nf < 4; nf++)
                    mma8(acc[mf][nf], Af[mf],
                         Bf[nf >> 1][(nf & 1) * 2], Bf[nf >> 1][(nf & 1) * 2 + 1]);
        }
    }
    __syncthreads();

    // epilogue: bias (+ GELU + tf32 round for layer 1), direct float2 stores
    int gq = lid >> 2, t4 = lid & 3;
#pragma unroll
    for (int mf = 0; mf < 4; mf++) {
#pragma unroll
        for (int nf = 0; nf < 4; nf++) {
            int ccol = warp_n * 32 + nf * 8 + t4 * 2;
            float bv0 = bsm[ccol], bv1 = bsm[ccol + 1];
            int grow = m0 + warp_m * 64 + mf * 16 + gq;
            int gcol = n0 + ccol;
#pragma unroll
            for (int h = 0; h < 2; h++) {  // h=0: rows g, h=1: rows g+8
                float v0 = acc[mf][nf][h * 2 + 0] + bv0;
                float v1 = acc[mf][nf][h * 2 + 1] + bv1;
                if (GELU_ROUND) {
                    v0 = rna_tf32(gelu_tanh(v0));
                    v1 = rna_tf32(gelu_tanh(v1));
                }
                float2 o = make_float2(v0, v1);
                *(float2*)(C + (size_t)(grow + h * 8) * N + gcol) = o;
            }
        }
    }
}

// ---------------- launch ----------------
extern "C" void kernel_launch(void* const* d_in, const int* in_sizes, int n_in,
                              void* d_out, int out_size) {
    const float* x  = (const float*)d_in[0];
    const float* W1 = (const float*)d_in[1];
    const float* b1 = (const float*)d_in[2];
    const float* W2 = (const float*)d_in[3];
    const float* b2 = (const float*)d_in[4];
    float* y = (float*)d_out;

    float *w1t, *w2t, *h, *xr;
    cudaGetSymbolAddress((void**)&w1t, g_W1T);
    cudaGetSymbolAddress((void**)&w2t, g_W2T);
    cudaGetSymbolAddress((void**)&h,   g_h);
    cudaGetSymbolAddress((void**)&xr,  g_xr);

    cudaFuncSetAttribute(ffn_gemm<true>,  cudaFuncAttributeMaxDynamicSharedMemorySize, SMEM_TOTAL);
    cudaFuncSetAttribute(ffn_gemm<false>, cudaFuncAttributeMaxDynamicSharedMemorySize, SMEM_TOTAL);

    // W1 [DM,DF] -> W1T [DF,DM];  W2 [DF,DM] -> W2T [DM,DF]  (tf32-rounded)
    transpose_k<<<dim3(DF / 32, DM / 32), 256>>>(W1, w1t, DM, DF);
    transpose_k<<<dim3(DM / 32, DF / 32), 256>>>(W2, w2t, DF, DM);
    // x -> xr (tf32-rounded)
    {
        int n4 = TOKENS * DM / 4;
        round_k<<<(n4 + 255) / 256, 256>>>(x, xr, n4);
    }

    // h = round(gelu(x @ W1 + b1))
    ffn_gemm<true><<<(DF / TN) * (TOKENS / TM), 256, SMEM_TOTAL>>>(
        xr, w1t, b1, h, TOKENS, DF, DM);
    // y = h @ W2 + b2
    ffn_gemm<false><<<(DM / TN) * (TOKENS / TM), 256, SMEM_TOTAL>>>(
        h, w2t, b2, y, TOKENS, DM, DF);
}

// round 4
// speedup vs baseline: 1.0035x; 1.0035x over previous
#include <cuda_runtime.h>
#include <cstdint>

#define TOKENS 4096
#define DM 4096
#define DF 16384

// Scratch (device globals: allocation-free rule)
__device__ float g_W1T[(size_t)DF * DM];    // W1^T: [DF][DM], tf32-rounded
__device__ float g_W2T[(size_t)DM * DF];    // W2^T: [DM][DF], tf32-rounded
__device__ float g_h[(size_t)TOKENS * DF];  // intermediate activations (tf32-rounded)
__device__ float g_xr[(size_t)TOKENS * DM]; // x, tf32-rounded

// ---------------- helpers ----------------
__device__ __forceinline__ uint32_t smem_u32(const void* p) {
    uint32_t a;
    asm("{ .reg .u64 t; cvta.to.shared.u64 t, %1; cvt.u32.u64 %0, t; }" : "=r"(a) : "l"(p));
    return a;
}
__device__ __forceinline__ uint32_t sw128(uint32_t off) { return off ^ ((off >> 3) & 0x70); }

__device__ __forceinline__ float rna_tf32(float x) {
    uint32_t u;
    asm("cvt.rna.tf32.f32 %0, %1;" : "=r"(u) : "f"(x));
    return __uint_as_float(u);
}

__device__ __forceinline__ void cp16(uint32_t s, const void* g) {
    asm volatile("cp.async.cg.shared.global [%0], [%1], 16;" :: "r"(s), "l"(g));
}
#define CP_COMMIT() asm volatile("cp.async.commit_group;" ::: "memory")
#define CP_WAIT(n)  asm volatile("cp.async.wait_group %0;" :: "n"(n) : "memory")

#define LDSM4(r, addr) \
    asm volatile("ldmatrix.sync.aligned.m8n8.x4.shared.b16 {%0,%1,%2,%3}, [%4];" \
        : "=r"((r)[0]), "=r"((r)[1]), "=r"((r)[2]), "=r"((r)[3]) : "r"(addr))

__device__ __forceinline__ void mma8(float* c, const uint32_t* a, uint32_t b0, uint32_t b1) {
    asm volatile(
        "mma.sync.aligned.m16n8k8.row.col.f32.tf32.tf32.f32 "
        "{%0,%1,%2,%3}, {%4,%5,%6,%7}, {%8,%9}, {%0,%1,%2,%3};"
        : "+f"(c[0]), "+f"(c[1]), "+f"(c[2]), "+f"(c[3])
        : "r"(a[0]), "r"(a[1]), "r"(a[2]), "r"(a[3]), "r"(b0), "r"(b1));
}

__device__ __forceinline__ float gelu_tanh(float v) {
    float u = 0.7978845608028654f * (v + 0.044715f * v * v * v);
    float e = __expf(-2.0f * fabsf(u));
    float t = (1.0f - e) / (1.0f + e);
    t = copysignf(t, u);
    return 0.5f * v * (1.0f + t);
}

// ---------------- transpose + tf32 round: src[R][C] -> dst[C][R] ----------------
__global__ void transpose_k(const float* __restrict__ src, float* __restrict__ dst,
                            int R, int C) {
    __shared__ float tile[32][33];
    int c0 = blockIdx.x * 32, r0 = blockIdx.y * 32;
    int tx = threadIdx.x & 31, ty = threadIdx.x >> 5;  // 256 threads
#pragma unroll
    for (int i = 0; i < 32; i += 8)
        tile[ty + i][tx] = src[(size_t)(r0 + ty + i) * C + c0 + tx];
    __syncthreads();
#pragma unroll
    for (int i = 0; i < 32; i += 8)
        dst[(size_t)(c0 + ty + i) * R + r0 + tx] = rna_tf32(tile[tx][ty + i]);
}

// ---------------- tf32 round (elementwise, float4) ----------------
__global__ void round_k(const float* __restrict__ src, float* __restrict__ dst, int n4) {
    int i = blockIdx.x * blockDim.x + threadIdx.x;
    if (i < n4) {
        float4 v = ((const float4*)src)[i];
        v.x = rna_tf32(v.x); v.y = rna_tf32(v.y);
        v.z = rna_tf32(v.z); v.w = rna_tf32(v.w);
        ((float4*)dst)[i] = v;
    }
}

// ---------------- tf32 mma.sync GEMM ----------------
// C[M,N] = act(A[M,K] @ Bt[N,K]^T + bias); A, Bt K-major row-major, K%32==0.
constexpr int TM = 128, TN = 128, TK = 32, NSTG = 3;
constexpr int A_BYTES = TM * TK * 4;             // 16384
constexpr int B_BYTES = TN * TK * 4;             // 16384
constexpr int STAGE_BYTES = A_BYTES + B_BYTES;   // 32768
constexpr int SM_BIAS   = 0;                     // 128 floats
constexpr int SM_STAGES = 1024;
constexpr int SMEM_TOTAL = SM_STAGES + NSTG * STAGE_BYTES;  // 99328

template <bool GELU_ROUND>
__global__ void __launch_bounds__(256)
ffn_gemm(const float* __restrict__ A, const float* __restrict__ Bt,
         const float* __restrict__ bias, float* __restrict__ C,
         int M, int N, int K) {
    extern __shared__ char smem[];
    uint32_t sb = smem_u32(smem);
    int tid = threadIdx.x;
    int wid = tid >> 5, lid = tid & 31;
    int warp_m = wid & 1, warp_n = wid >> 1;   // 2 x 4 warp grid, warp tile 64x32

    // L2-friendly tile swizzle: groups of 8 N-tiles x all M-tiles
    int tiles_m = M / TM;
    const int GW = 8;
    int per_group = GW * tiles_m;
    int g = blockIdx.x / per_group;
    int r = blockIdx.x % per_group;
    int nt = g * GW + (r % GW);
    int mt = r / GW;
    int m0 = mt * TM, n0 = nt * TN;

    // bias tile -> smem
    float* bsm = (float*)(smem + SM_BIAS);
    if (tid < TN) bsm[tid] = bias[n0 + tid];

    // per-lane ldmatrix byte offsets, UNSWIZZLED (swizzle applied at use site,
    // because sw128(off + d) != sw128(off) + d when the XOR mask carries).
    // A frag m16n8k8 tf32: r0=(g,t4) r1=(g+8,t4) r2=(g,t4+4) r3=(g+8,t4+4)
    uint32_t aoff[4], boff[2];
    {
        int l = lid;
        int rA = ((l >> 3) & 1) * 8 + (l & 7);
        int cA = ((l >> 4) & 1) * 4;
#pragma unroll
        for (int mf = 0; mf < 4; mf++)
            aoff[mf] = (uint32_t)(warp_m * 64 + mf * 16 + rA) * 128 + cA * 4;
        int rB = ((l >> 4) & 1) * 8 + (l & 7);
        int cB = ((l >> 3) & 1) * 4;
#pragma unroll
        for (int np = 0; np < 2; np++)
            boff[np] = (uint32_t)(warp_n * 32 + np * 16 + rB) * 128 + cB * 4;
    }

    float acc[4][4][4];
#pragma unroll
    for (int i = 0; i < 4; i++)
#pragma unroll
        for (int j = 0; j < 4; j++)
#pragma unroll
            for (int k = 0; k < 4; k++) acc[i][j][k] = 0.0f;

    int nch = K / TK;

    auto load_stage = [&](int stage, int ch) {
        uint32_t abase = sb + SM_STAGES + stage * STAGE_BYTES;
        uint32_t bbase = abase + A_BYTES;
        const float* Ap = A + (size_t)m0 * K + ch * TK;
        const float* Bp = Bt + (size_t)n0 * K + ch * TK;
#pragma unroll
        for (int j = 0; j < 4; j++) {  // A: 1024 x 16B
            int e = tid + j * 256;
            int row = e >> 3, c = e & 7;
            cp16(abase + sw128(row * 128 + c * 16), Ap + (size_t)row * K + c * 4);
        }
#pragma unroll
        for (int j = 0; j < 4; j++) {  // B: 1024 x 16B
            int e = tid + j * 256;
            int row = e >> 3, c = e & 7;
            cp16(bbase + sw128(row * 128 + c * 16), Bp + (size_t)row * K + c * 4);
        }
    };

    // prologue
    for (int s = 0; s < NSTG - 1; s++) { load_stage(s, s); CP_COMMIT(); }

    for (int ch = 0; ch < nch; ch++) {
        CP_WAIT(1);           // stage ch resident (NSTG-2 pending)
        __syncthreads();      // all lanes see it; prior compute on overwrite-target done

        int pf = ch + NSTG - 1;
        if (pf < nch) load_stage(pf % NSTG, pf);
        CP_COMMIT();

        uint32_t ab = sb + SM_STAGES + (ch % NSTG) * STAGE_BYTES;
        uint32_t bb = ab + A_BYTES;
#pragma unroll
        for (int ks = 0; ks < 4; ks++) {
            uint32_t Af[4][4], Bf[2][4];
#pragma unroll
            for (int mf = 0; mf < 4; mf++)
                LDSM4(Af[mf], ab + sw128(aoff[mf] + ks * 32));
#pragma unroll
            for (int np = 0; np < 2; np++)
                LDSM4(Bf[np], bb + sw128(boff[np] + ks * 32));
#pragma unroll
            for (int mf = 0; mf < 4; mf++)
#pragma unroll
                for (int nf = 0; nf < 4; nf++)
                    mma8(acc[mf][nf], Af[mf],
                         Bf[nf >> 1][(nf & 1) * 2], Bf[nf >> 1][(nf & 1) * 2 + 1]);
        }
    }
    __syncthreads();

    // epilogue: bias (+ GELU + tf32 round for layer 1), direct float2 stores
    int gq = lid >> 2, t4 = lid & 3;
#pragma unroll
    for (int mf = 0; mf < 4; mf++) {
#pragma unroll
        for (int nf = 0; nf < 4; nf++) {
            int ccol = warp_n * 32 + nf * 8 + t4 * 2;
            float bv0 = bsm[ccol], bv1 = bsm[ccol + 1];
            int grow = m0 + warp_m * 64 + mf * 16 + gq;
            int gcol = n0 + ccol;
#pragma unroll
            for (int h = 0; h < 2; h++) {  // h=0: rows g, h=1: rows g+8
                float v0 = acc[mf][nf][h * 2 + 0] + bv0;
                float v1 = acc[mf][nf][h * 2 + 1] + bv1;
                if (GELU_ROUND) {
                    v0 = rna_tf32(gelu_tanh(v0));
                    v1 = rna_tf32(gelu_tanh(v1));
                }
                float2 o = make_float2(v0, v1);
                *(float2*)(C + (size_t)(grow + h * 8) * N + gcol) = o;
            }
        }
    }
}

// ---------------- launch ----------------
extern "C" void kernel_launch(void* const* d_in, const int* in_sizes, int n_in,
                              void* d_out, int out_size) {
    const float* x  = (const float*)d_in[0];
    const float* W1 = (const float*)d_in[1];
    const float* b1 = (const float*)d_in[2];
    const float* W2 = (const float*)d_in[3];
    const float* b2 = (const float*)d_in[4];
    float* y = (float*)d_out;

    float *w1t, *w2t, *h, *xr;
    cudaGetSymbolAddress((void**)&w1t, g_W1T);
    cudaGetSymbolAddress((void**)&w2t, g_W2T);
    cudaGetSymbolAddress((void**)&h,   g_h);
    cudaGetSymbolAddress((void**)&xr,  g_xr);

    cudaFuncSetAttribute(ffn_gemm<true>,  cudaFuncAttributeMaxDynamicSharedMemorySize, SMEM_TOTAL);
    cudaFuncSetAttribute(ffn_gemm<false>, cudaFuncAttributeMaxDynamicSharedMemorySize, SMEM_TOTAL);

    // W1 [DM,DF] -> W1T [DF,DM];  W2 [DF,DM] -> W2T [DM,DF]  (tf32-rounded)
    transpose_k<<<dim3(DF / 32, DM / 32), 256>>>(W1, w1t, DM, DF);
    transpose_k<<<dim3(DM / 32, DF / 32), 256>>>(W2, w2t, DF, DM);
    // x -> xr (tf32-rounded)
    {
        int n4 = TOKENS * DM / 4;
        round_k<<<(n4 + 255) / 256, 256>>>(x, xr, n4);
    }

    // h = round(gelu(x @ W1 + b1))
    ffn_gemm<true><<<(DF / TN) * (TOKENS / TM), 256, SMEM_TOTAL>>>(
        xr, w1t, b1, h, TOKENS, DF, DM);
    // y = h @ W2 + b2
    ffn_gemm<false><<<(DM / TN) * (TOKENS / TM), 256, SMEM_TOTAL>>>(
        h, w2t, b2, y, TOKENS, DM, DF);
}

// round 5
// speedup vs baseline: 2.0162x; 2.0091x over previous
#include <cuda_runtime.h>
#include <cuda_fp16.h>
#include <cstdint>

#define TOKENS 4096
#define DM 4096
#define DF 16384

// Scratch (device globals: allocation-free rule)
__device__ __half g_W1T[(size_t)DF * DM];    // W1^T: [DF][DM], fp16
__device__ __half g_W2T[(size_t)DM * DF];    // W2^T: [DM][DF], fp16
__device__ __half g_h[(size_t)TOKENS * DF];  // intermediate activations, fp16
__device__ __half g_xh[(size_t)TOKENS * DM]; // x, fp16

// ---------------- helpers ----------------
__device__ __forceinline__ uint32_t smem_u32(const void* p) {
    uint32_t a;
    asm("{ .reg .u64 t; cvta.to.shared.u64 t, %1; cvt.u32.u64 %0, t; }" : "=r"(a) : "l"(p));
    return a;
}
// SW64 swizzle for 64-byte rows: banks (4r + c^((r>>1)&3)) % 8 all-distinct over 8 rows
__device__ __forceinline__ uint32_t sw64(uint32_t off) { return off ^ ((off >> 3) & 0x30); }

__device__ __forceinline__ void cp16(uint32_t s, const void* g) {
    asm volatile("cp.async.cg.shared.global [%0], [%1], 16;" :: "r"(s), "l"(g));
}
#define CP_COMMIT() asm volatile("cp.async.commit_group;" ::: "memory")
#define CP_WAIT(n)  asm volatile("cp.async.wait_group %0;" :: "n"(n) : "memory")

#define LDSM4(r, addr) \
    asm volatile("ldmatrix.sync.aligned.m8n8.x4.shared.b16 {%0,%1,%2,%3}, [%4];" \
        : "=r"((r)[0]), "=r"((r)[1]), "=r"((r)[2]), "=r"((r)[3]) : "r"(addr))

__device__ __forceinline__ void mma16(float* c, const uint32_t* a, uint32_t b0, uint32_t b1) {
    asm volatile(
        "mma.sync.aligned.m16n8k16.row.col.f32.f16.f16.f32 "
        "{%0,%1,%2,%3}, {%4,%5,%6,%7}, {%8,%9}, {%0,%1,%2,%3};"
        : "+f"(c[0]), "+f"(c[1]), "+f"(c[2]), "+f"(c[3])
        : "r"(a[0]), "r"(a[1]), "r"(a[2]), "r"(a[3]), "r"(b0), "r"(b1));
}

__device__ __forceinline__ float gelu_tanh(float v) {
    float u = 0.7978845608028654f * (v + 0.044715f * v * v * v);
    float e = __expf(-2.0f * fabsf(u));
    float t = (1.0f - e) / (1.0f + e);
    t = copysignf(t, u);
    return 0.5f * v * (1.0f + t);
}

// ---------------- transpose + fp16 convert: src[R][C] -> dst[C][R] ----------------
__global__ void transpose_h(const float* __restrict__ src, __half* __restrict__ dst,
                            int R, int C) {
    __shared__ float tile[32][33];
    int c0 = blockIdx.x * 32, r0 = blockIdx.y * 32;
    int tx = threadIdx.x & 31, ty = threadIdx.x >> 5;  // 256 threads
#pragma unroll
    for (int i = 0; i < 32; i += 8)
        tile[ty + i][tx] = src[(size_t)(r0 + ty + i) * C + c0 + tx];
    __syncthreads();
#pragma unroll
    for (int i = 0; i < 32; i += 8)
        dst[(size_t)(c0 + ty + i) * R + r0 + tx] = __float2half_rn(tile[tx][ty + i]);
}

// ---------------- fp32 -> fp16 elementwise ----------------
__global__ void tohalf_k(const float* __restrict__ src, __half* __restrict__ dst, int n4) {
    int i = blockIdx.x * blockDim.x + threadIdx.x;
    if (i < n4) {
        float4 v = ((const float4*)src)[i];
        __half2 lo = __floats2half2_rn(v.x, v.y);
        __half2 hi = __floats2half2_rn(v.z, v.w);
        ((__half2*)dst)[i * 2 + 0] = lo;
        ((__half2*)dst)[i * 2 + 1] = hi;
    }
}

// ---------------- fp16 mma.sync GEMM ----------------
// C[M,N] = act(A[M,K] @ Bt[N,K]^T + bias); A, Bt fp16 K-major row-major, K%32==0.
constexpr int TM = 128, TN = 128, TK = 32, NSTG = 4;
constexpr int A_BYTES = TM * TK * 2;             // 8192
constexpr int B_BYTES = TN * TK * 2;             // 8192
constexpr int STAGE_BYTES = A_BYTES + B_BYTES;   // 16384
constexpr int SM_BIAS   = 0;                     // 128 floats
constexpr int SM_STAGES = 1024;
constexpr int SMEM_TOTAL = SM_STAGES + NSTG * STAGE_BYTES;  // 66560 -> 2 CTAs/SM

template <bool GELU_HALF_OUT>
__global__ void __launch_bounds__(256, 2)
ffn_gemm(const __half* __restrict__ A, const __half* __restrict__ Bt,
         const float* __restrict__ bias, void* __restrict__ Cv,
         int M, int N, int K) {
    extern __shared__ char smem[];
    uint32_t sb = smem_u32(smem);
    int tid = threadIdx.x;
    int wid = tid >> 5, lid = tid & 31;
    int warp_m = wid & 1, warp_n = wid >> 1;   // 2 x 4 warp grid, warp tile 64x32

    // L2-friendly tile swizzle: groups of 8 N-tiles x all M-tiles
    int tiles_m = M / TM;
    const int GW = 8;
    int per_group = GW * tiles_m;
    int g = blockIdx.x / per_group;
    int r = blockIdx.x % per_group;
    int nt = g * GW + (r % GW);
    int mt = r / GW;
    int m0 = mt * TM, n0 = nt * TN;

    // bias tile -> smem
    float* bsm = (float*)(smem + SM_BIAS);
    if (tid < TN) bsm[tid] = bias[n0 + tid];

    // ldmatrix per-lane UNSWIZZLED byte offsets (swizzle at use site; adds don't
    // commute with the XOR).
    // A x4 (16x16 halves): mat0=rows0-7,k0-7  mat1=rows8-15,k0-7
    //                      mat2=rows0-7,k8-15 mat3=rows8-15,k8-15  -> a0..a3
    // B x4 (n16xk16):      mat0=n0-7,k0-7 mat1=n0-7,k8-15
    //                      mat2=n8-15,k0-7 mat3=n8-15,k8-15        -> b0,b1 per n-octet
    uint32_t aoff[4], boff[2];
    {
        int l = lid;
        int matA = l >> 3, rA = l & 7;
        int rowA = (matA & 1) * 8 + rA;
        int colA = (matA >> 1) * 16;
#pragma unroll
        for (int mf = 0; mf < 4; mf++)
            aoff[mf] = (uint32_t)(warp_m * 64 + mf * 16 + rowA) * 64 + colA;
        int nB = ((l >> 4) & 1) * 8 + (l & 7);
        int colB = ((l >> 3) & 1) * 16;
#pragma unroll
        for (int np = 0; np < 2; np++)
            boff[np] = (uint32_t)(warp_n * 32 + np * 16 + nB) * 64 + colB;
    }

    float acc[4][4][4];
#pragma unroll
    for (int i = 0; i < 4; i++)
#pragma unroll
        for (int j = 0; j < 4; j++)
#pragma unroll
            for (int k = 0; k < 4; k++) acc[i][j][k] = 0.0f;

    int nch = K / TK;

    auto load_stage = [&](int stage, int ch) {
        uint32_t abase = sb + SM_STAGES + stage * STAGE_BYTES;
        uint32_t bbase = abase + A_BYTES;
        const __half* Ap = A + (size_t)m0 * K + ch * TK;
        const __half* Bp = Bt + (size_t)n0 * K + ch * TK;
#pragma unroll
        for (int j = 0; j < 2; j++) {  // A: 512 x 16B
            int e = tid + j * 256;
            int row = e >> 2, c = e & 3;
            cp16(abase + sw64(row * 64 + c * 16), Ap + (size_t)row * K + c * 8);
        }
#pragma unroll
        for (int j = 0; j < 2; j++) {  // B: 512 x 16B
            int e = tid + j * 256;
            int row = e >> 2, c = e & 3;
            cp16(bbase + sw64(row * 64 + c * 16), Bp + (size_t)row * K + c * 8);
        }
    };

    // prologue: stages 0..NSTG-2
    for (int s = 0; s < NSTG - 1; s++) { load_stage(s, s); CP_COMMIT(); }

    for (int ch = 0; ch < nch; ch++) {
        CP_WAIT(NSTG - 2);    // stage ch resident
        __syncthreads();

        int pf = ch + NSTG - 1;
        if (pf < nch) load_stage(pf % NSTG, pf);
        CP_COMMIT();

        uint32_t ab = sb + SM_STAGES + (ch % NSTG) * STAGE_BYTES;
        uint32_t bb = ab + A_BYTES;
#pragma unroll
        for (int ks = 0; ks < 2; ks++) {   // two k16 steps per TK=32 chunk
            uint32_t Af[4][4], Bf[2][4];
#pragma unroll
            for (int mf = 0; mf < 4; mf++)
                LDSM4(Af[mf], ab + sw64(aoff[mf] + ks * 32));
#pragma unroll
            for (int np = 0; np < 2; np++)
                LDSM4(Bf[np], bb + sw64(boff[np] + ks * 32));
#pragma unroll
            for (int mf = 0; mf < 4; mf++)
#pragma unroll
                for (int nf = 0; nf < 4; nf++)
                    mma16(acc[mf][nf], Af[mf],
                          Bf[nf >> 1][(nf & 1) * 2], Bf[nf >> 1][(nf & 1) * 2 + 1]);
        }
    }
    __syncthreads();

    // epilogue: bias (+ GELU, fp16 out for layer 1; fp32 out for layer 2)
    int gq = lid >> 2, t4 = lid & 3;
#pragma unroll
    for (int mf = 0; mf < 4; mf++) {
#pragma unroll
        for (int nf = 0; nf < 4; nf++) {
            int ccol = warp_n * 32 + nf * 8 + t4 * 2;
            float bv0 = bsm[ccol], bv1 = bsm[ccol + 1];
            int grow = m0 + warp_m * 64 + mf * 16 + gq;
            int gcol = n0 + ccol;
#pragma unroll
            for (int h = 0; h < 2; h++) {  // h=0: row g, h=1: row g+8
                float v0 = acc[mf][nf][h * 2 + 0] + bv0;
                float v1 = acc[mf][nf][h * 2 + 1] + bv1;
                if (GELU_HALF_OUT) {
                    __half2 o = __floats2half2_rn(gelu_tanh(v0), gelu_tanh(v1));
                    *(__half2*)((__half*)Cv + (size_t)(grow + h * 8) * N + gcol) = o;
                } else {
                    float2 o = make_float2(v0, v1);
                    *(float2*)((float*)Cv + (size_t)(grow + h * 8) * N + gcol) = o;
                }
            }
        }
    }
}

// ---------------- launch ----------------
extern "C" void kernel_launch(void* const* d_in, const int* in_sizes, int n_in,
                              void* d_out, int out_size) {
    const float* x  = (const float*)d_in[0];
    const float* W1 = (const float*)d_in[1];
    const float* b1 = (const float*)d_in[2];
    const float* W2 = (const float*)d_in[3];
    const float* b2 = (const float*)d_in[4];
    float* y = (float*)d_out;

    __half *w1t, *w2t, *h, *xh;
    cudaGetSymbolAddress((void**)&w1t, g_W1T);
    cudaGetSymbolAddress((void**)&w2t, g_W2T);
    cudaGetSymbolAddress((void**)&h,   g_h);
    cudaGetSymbolAddress((void**)&xh,  g_xh);

    cudaFuncSetAttribute(ffn_gemm<true>,  cudaFuncAttributeMaxDynamicSharedMemorySize, SMEM_TOTAL);
    cudaFuncSetAttribute(ffn_gemm<false>, cudaFuncAttributeMaxDynamicSharedMemorySize, SMEM_TOTAL);

    // W1 [DM,DF] -> W1T [DF,DM];  W2 [DF,DM] -> W2T [DM,DF]  (fp16)
    transpose_h<<<dim3(DF / 32, DM / 32), 256>>>(W1, w1t, DM, DF);
    transpose_h<<<dim3(DM / 32, DF / 32), 256>>>(W2, w2t, DF, DM);
    // x -> fp16
    {
        int n4 = TOKENS * DM / 4;
        tohalf_k<<<(n4 + 255) / 256, 256>>>(x, xh, n4);
    }

    // h = fp16(gelu(x @ W1 + b1))
    ffn_gemm<true><<<(DF / TN) * (TOKENS / TM), 256, SMEM_TOTAL>>>(
        xh, w1t, b1, h, TOKENS, DF, DM);
    // y = h @ W2 + b2
    ffn_gemm<false><<<(DM / TN) * (TOKENS / TM), 256, SMEM_TOTAL>>>(
        h, w2t, b2, y, TOKENS, DM, DF);
}